// round 11
// baseline (speedup 1.0000x reference)
#include <cuda_runtime.h>
#include <cuda_bf16.h>
#include <cstdint>
#include <math.h>

#define B_    8
#define T_    2048
#define NB_   22
#define D_    128
#define O_    128      // WIDTH*2
#define FREQ_ 1025
#define NFFT  2048
#define N2    1024
#define HOP_  512
#define OUTL  1048064  // HOP*(T-1)

// Scratch (static device globals; no runtime allocation)
__device__ __nv_bfloat16 g_band[(size_t)B_ * T_ * NB_ * O_];  // band residual (no bias), bf16
__device__ __nv_bfloat16 g_Wt[(size_t)NB_ * 128 * 128];       // W transposed [n][o][d], bf16
__device__ float g_frames[(size_t)B_ * T_ * NFFT];            // windowed istft frames

// Precomputed tables (filled by k_init every launch; deterministic)
__device__ float2 g_tw[5][256];   // FFT stage twiddles w1
__device__ float2 g_pk[1024];     // hermitian pack twiddles (cos, sin) of pi*j/1024
__device__ float  g_win2[2048];   // hann^2
__device__ float2 g_winp[1024];   // (win[2m], win[2m+1]) * (1/2048)
__device__ float4 g_mb[FREQ_];    // (bias_r*invw, bias_i*invw, invw, 0) per freq

#define ZSTR 136   // padded bf16 row stride

// ---------------------------------------------------------------------------
// K0: fill twiddle/window/mask-bias tables
// ---------------------------------------------------------------------------
__global__ void k_init(const float* __restrict__ bias)
{
    int i = blockIdx.x * 256 + threadIdx.x;   // 0..2047
    if (i < 2048) {
        float w = 0.5f - 0.5f * cospif((float)i * (1.0f / 1024.0f));
        g_win2[i] = w * w;
    }
    if (i < 1024) {
        float s, c;
        sincospif((float)i * (1.0f / 1024.0f), &s, &c);
        g_pk[i] = make_float2(c, s);
        const float invN = 1.0f / 2048.0f;
        float w0 = 0.5f - 0.5f * cospif((float)(2 * i) * (1.0f / 1024.0f));
        float w1 = 0.5f - 0.5f * cospif((float)(2 * i + 1) * (1.0f / 1024.0f));
        g_winp[i] = make_float2(w0 * invN, w1 * invN);
    }
    if (i < 256) {
#pragma unroll
        for (int st = 0; st < 5; st++) {
            int ns = 1 << (2 * st);
            int base = i & (ns - 1);
            float s, c;
            sincospif((float)base / (float)(2 * ns), &s, &c);
            g_tw[st][i] = make_float2(c, s);
        }
    }
    if (i < FREQ_) {
        int f = i;
        float br = 0.0f, bi = 0.0f;
        int cnt = 0;
        int n1 = f / 48; if (n1 > 20) n1 = 20;
        int n0 = (f >= 63) ? (f - 63 + 47) / 48 : 0;
        for (int nn = n0; nn <= n1; nn++) {
            int col = f - 48 * nn;
            br += bias[nn * 128 + 2 * col];
            bi += bias[nn * 128 + 2 * col + 1];
            cnt++;
        }
        if (f >= 961) {
            int col = f - 961;
            br += bias[21 * 128 + 2 * col];
            bi += bias[21 * 128 + 2 * col + 1];
            cnt++;
        }
        float invw = 1.0f / (float)(cnt > 0 ? cnt : 1);
        g_mb[f] = make_float4(br * invw, bi * invw, invw, 0.0f);
    }
}

// ---------------------------------------------------------------------------
// K0b: transpose W (fp32 [n][d][o]) -> g_Wt (bf16 [n][o][d]), once per band.
// ---------------------------------------------------------------------------
__global__ __launch_bounds__(256) void k_prep(const float* __restrict__ W)
{
    __shared__ __nv_bfloat16 tile[128 * ZSTR];
    const int n = blockIdx.x;
    const int tid = threadIdx.x;
#pragma unroll
    for (int i = 0; i < 64; i++) {
        int idx = tid + 256 * i;          // 0..16383
        int d = idx >> 7;
        int o = idx & 127;
        tile[o * ZSTR + d] = __float2bfloat16(W[(size_t)n * 16384 + idx]);
    }
    __syncthreads();
#pragma unroll
    for (int i = 0; i < 8; i++) {
        int idx = tid + 256 * i;          // 0..2047 uint4s
        int row = idx >> 4;
        int c = idx & 15;
        *(uint4*)(g_Wt + (size_t)n * 16384 + row * 128 + c * 8) =
            *(const uint4*)&tile[row * ZSTR + c * 8];
    }
}

// ---------------------------------------------------------------------------
// K1: band GEMM via bf16 mma.sync (m16n8k16) + ldmatrix fragment loads.
// ---------------------------------------------------------------------------
__global__ __launch_bounds__(256) void k_gemm(const float* __restrict__ z)
{
    extern __shared__ char smraw[];
    __nv_bfloat16* Za = (__nv_bfloat16*)smraw;            // [128][ZSTR]
    __nv_bfloat16* Wt = Za + 128 * ZSTR;                  // [128][ZSTR]  (o-major)

    const int n  = blockIdx.y;
    const int b  = blockIdx.z;
    const int t0 = blockIdx.x * 128;
    const int tid = threadIdx.x;

#pragma unroll
    for (int i = 0; i < 16; i++) {
        int idx = tid + 256 * i;          // 0..4095 float4s
        int r = idx >> 5;
        int c4 = idx & 31;
        float4 v = *(const float4*)(z + (((size_t)(b * T_ + t0 + r)) * NB_ + n) * 128 + c4 * 4);
        __nv_bfloat162* dst = (__nv_bfloat162*)&Za[r * ZSTR + c4 * 4];
        dst[0] = __float22bfloat162_rn(make_float2(v.x, v.y));
        dst[1] = __float22bfloat162_rn(make_float2(v.z, v.w));
    }

#pragma unroll
    for (int i = 0; i < 8; i++) {
        int idx = tid + 256 * i;          // 0..2047 uint4s
        int row = idx >> 4;
        int c = idx & 15;
        *(uint4*)&Wt[row * ZSTR + c * 8] =
            *(const uint4*)(g_Wt + (size_t)n * 16384 + row * 128 + c * 8);
    }
    __syncthreads();

    const int w    = tid >> 5;
    const int lane = tid & 31;
    const int gr   = lane >> 2;
    const int qc   = (lane & 3) * 2;
    const int r0   = w * 16;

    const int l8 = lane & 7;
    const int g  = lane >> 3;
    uint32_t za_s = (uint32_t)__cvta_generic_to_shared(Za);
    uint32_t wt_s = (uint32_t)__cvta_generic_to_shared(Wt);
    uint32_t aaddr = za_s + (uint32_t)(((r0 + l8 + 8 * (g & 1)) * ZSTR + 8 * (g >> 1)) * 2);
    uint32_t baddr0 = wt_s + (uint32_t)(((l8 + 8 * (g >> 1)) * ZSTR + 8 * (g & 1)) * 2);

    float acc[16][4];
#pragma unroll
    for (int nt = 0; nt < 16; nt++)
#pragma unroll
        for (int j = 0; j < 4; j++) acc[nt][j] = 0.0f;

#pragma unroll
    for (int ks = 0; ks < 8; ks++) {
        const uint32_t koff = ks * 16 * 2;
        uint32_t a0, a1, a2, a3;
        asm volatile("ldmatrix.sync.aligned.m8n8.x4.shared.b16 {%0,%1,%2,%3}, [%4];"
                     : "=r"(a0), "=r"(a1), "=r"(a2), "=r"(a3) : "r"(aaddr + koff));
#pragma unroll
        for (int ntp = 0; ntp < 8; ntp++) {
            uint32_t q0, q1, q2, q3;
            uint32_t ba = baddr0 + (uint32_t)(ntp * 16 * ZSTR * 2) + koff;
            asm volatile("ldmatrix.sync.aligned.m8n8.x4.shared.b16 {%0,%1,%2,%3}, [%4];"
                         : "=r"(q0), "=r"(q1), "=r"(q2), "=r"(q3) : "r"(ba));
            asm volatile(
                "mma.sync.aligned.m16n8k16.row.col.f32.bf16.bf16.f32 "
                "{%0,%1,%2,%3}, {%4,%5,%6,%7}, {%8,%9}, {%0,%1,%2,%3};\n"
                : "+f"(acc[2 * ntp][0]), "+f"(acc[2 * ntp][1]),
                  "+f"(acc[2 * ntp][2]), "+f"(acc[2 * ntp][3])
                : "r"(a0), "r"(a1), "r"(a2), "r"(a3), "r"(q0), "r"(q1));
            asm volatile(
                "mma.sync.aligned.m16n8k16.row.col.f32.bf16.bf16.f32 "
                "{%0,%1,%2,%3}, {%4,%5,%6,%7}, {%8,%9}, {%0,%1,%2,%3};\n"
                : "+f"(acc[2 * ntp + 1][0]), "+f"(acc[2 * ntp + 1][1]),
                  "+f"(acc[2 * ntp + 1][2]), "+f"(acc[2 * ntp + 1][3])
                : "r"(a0), "r"(a1), "r"(a2), "r"(a3), "r"(q2), "r"(q3));
        }
    }

    const int row0 = t0 + r0 + gr;
    const int row1 = row0 + 8;
#pragma unroll
    for (int nt = 0; nt < 16; nt++) {
        const int col = nt * 8 + qc;
        __nv_bfloat16* p0 = g_band + (((size_t)(b * T_ + row0)) * NB_ + n) * 128 + col;
        __nv_bfloat16* p1 = g_band + (((size_t)(b * T_ + row1)) * NB_ + n) * 128 + col;
        *(__nv_bfloat162*)p0 = __float22bfloat162_rn(make_float2(acc[nt][0], acc[nt][1]));
        *(__nv_bfloat162*)p1 = __float22bfloat162_rn(make_float2(acc[nt][2], acc[nt][3]));
    }
}

// ---------------------------------------------------------------------------
// K2: mask gather + complex mult + irfft(2048) + window.
// 64 threads/frame, 16 points/thread: stages (0+1) and (2+3) fused in
// registers, only 2 smem exchanges; stage 4 exits to global from registers.
// 2 frames per 128-thread block; single padded smem buffer per frame.
// ---------------------------------------------------------------------------
__device__ __forceinline__ float2 cmul(float2 a, float2 b) {
    return make_float2(a.x * b.x - a.y * b.y, a.x * b.y + a.y * b.x);
}
// padded address: rows of 16 complex, +2 complex pad per row
__device__ __forceinline__ int ad(int p) { return p + 2 * (p >> 4); }

__global__ __launch_bounds__(128) void k_fft(const float* __restrict__ mix)
{
    __shared__ __nv_bfloat162 bandv[2][NB_ * 64];   // 2 x 1408 pairs
    __shared__ float2 buf[2][1152];                 // 1024 + row padding

    const int fr = threadIdx.x >> 6;      // frame slot in block
    const int j0 = threadIdx.x & 63;      // 0..63 within frame
    const int frame = blockIdx.x * 2 + fr;
    const int b = frame >> 11;
    const int t = frame & 2047;

    // Load band residuals (bf16) via uint4 (352 per frame, 64 threads)
    {
        const uint4* src4 = (const uint4*)(g_band + (size_t)frame * (NB_ * O_));
        uint4* dst4 = (uint4*)bandv[fr];
#pragma unroll
        for (int i = 0; i < 6; i++) {
            int idx = j0 + 64 * i;
            if (idx < 352) dst4[idx] = src4[idx];
        }
    }
    __syncthreads();

    const float* mr = mix + ((size_t)(b * 2 + 0) * T_ + t) * FREQ_;
    const float* mi = mix + ((size_t)(b * 2 + 1) * T_ + t) * FREQ_;

    auto computeX = [&](int f) -> float2 {
        float sr = 0.0f, si = 0.0f;
        int n1 = f / 48; if (n1 > 20) n1 = 20;
        int n0 = (f >= 63) ? (f - 63 + 47) / 48 : 0;
        for (int nn = n0; nn <= n1; nn++) {
            int col = f - 48 * nn;
            float2 v = __bfloat1622float2(bandv[fr][nn * 64 + col]);
            sr += v.x; si += v.y;
        }
        if (f >= 961) {
            float2 v = __bfloat1622float2(bandv[fr][21 * 64 + (f - 961)]);
            sr += v.x; si += v.y;
        }
        float4 mb = g_mb[f];
        float maskr = fmaf(sr, mb.z, mb.x);
        float maski = fmaf(si, mb.z, mb.y);
        float xr = mr[f], xi = mi[f];
        return make_float2(maskr * xr - maski * xi, maskr * xi + maski * xr);
    };

    // Pack phase (unpadded layout): 8 pairs per thread
#pragma unroll
    for (int i = 0; i < 8; i++) {
        int j = j0 + 64 * i;
        if (j == 0) {
            float x0 = computeX(0).x;
            float xn = computeX(1024).x;
            buf[fr][0] = make_float2(x0 + xn, x0 - xn);
            float2 u = computeX(512);
            buf[fr][512] = make_float2(2.0f * u.x, -2.0f * u.y);
        } else {
            float2 u = computeX(j);
            float2 v = computeX(1024 - j);
            float Ar = u.x + v.x, Ai = u.y - v.y;
            float Dr = u.x - v.x, Di = u.y + v.y;
            float2 cs = g_pk[j];
            float c = cs.x, s = cs.y;
            buf[fr][j]        = make_float2(Ar - s * Dr - c * Di,  Ai + c * Dr - s * Di);
            buf[fr][1024 - j] = make_float2(Ar + s * Dr + c * Di, -Ai + c * Dr - s * Di);
        }
    }
    __syncthreads();

    float2 X[4][4], Y[4][4], Z[4][4];

#define RAD4(A0, A1, A2, A3, O0, O1, O2, O3)                                  \
    {                                                                         \
        float2 p_ = make_float2(A0.x + A2.x, A0.y + A2.y);                    \
        float2 m_ = make_float2(A0.x - A2.x, A0.y - A2.y);                    \
        float2 q_ = make_float2(A1.x + A3.x, A1.y + A3.y);                    \
        float2 r_ = make_float2(A1.x - A3.x, A1.y - A3.y);                    \
        O0 = make_float2(p_.x + q_.x, p_.y + q_.y);                           \
        O1 = make_float2(m_.x - r_.y, m_.y + r_.x);                           \
        O2 = make_float2(p_.x - q_.x, p_.y - q_.y);                          \
        O3 = make_float2(m_.x + r_.y, m_.y - r_.x);                           \
    }

    // ---- Stages 0+1 in registers ----
#pragma unroll
    for (int a = 0; a < 4; a++)
#pragma unroll
        for (int bb = 0; bb < 4; bb++)
            X[a][bb] = buf[fr][j0 + 64 * a + 256 * bb];
    __syncthreads();   // all pack reads done before padded overwrite

    // stage 0: butterfly over b, no twiddles (base=0)
#pragma unroll
    for (int a = 0; a < 4; a++)
        RAD4(X[a][0], X[a][1], X[a][2], X[a][3], Y[a][0], Y[a][1], Y[a][2], Y[a][3]);

    // stage 1: butterfly over a, twiddle base = k
#pragma unroll
    for (int k = 0; k < 4; k++) {
        float2 w1 = g_tw[1][k];
        float2 w2 = cmul(w1, w1);
        float2 w3 = cmul(w2, w1);
        float2 aa = Y[0][k];
        float2 bb = cmul(Y[1][k], w1);
        float2 cc = cmul(Y[2][k], w2);
        float2 dd = cmul(Y[3][k], w3);
        RAD4(aa, bb, cc, dd, Z[0][k], Z[1][k], Z[2][k], Z[3][k]);
    }

    // Exchange 1: positions 16*j0 + 4m + k (contiguous 16) -> padded rows, float4
    {
        float4* b4 = (float4*)&buf[fr][18 * j0];
#pragma unroll
        for (int m = 0; m < 4; m++) {
            b4[2 * m]     = make_float4(Z[m][0].x, Z[m][0].y, Z[m][1].x, Z[m][1].y);
            b4[2 * m + 1] = make_float4(Z[m][2].x, Z[m][2].y, Z[m][3].x, Z[m][3].y);
        }
    }
    __syncthreads();

    // ---- Stages 2+3 in registers ----
#pragma unroll
    for (int a = 0; a < 4; a++)
#pragma unroll
        for (int bb = 0; bb < 4; bb++)
            X[a][bb] = buf[fr][ad(j0 + 64 * a + 256 * bb)];
    __syncthreads();

    // stage 2: butterfly over b, base2 = j0 & 15 (same for all a)
    {
        float2 w1 = g_tw[2][j0];
        float2 w2 = cmul(w1, w1);
        float2 w3 = cmul(w2, w1);
#pragma unroll
        for (int a = 0; a < 4; a++) {
            float2 aa = X[a][0];
            float2 bb = cmul(X[a][1], w1);
            float2 cc = cmul(X[a][2], w2);
            float2 dd = cmul(X[a][3], w3);
            RAD4(aa, bb, cc, dd, Y[a][0], Y[a][1], Y[a][2], Y[a][3]);
        }
    }
    // stage 3: butterfly over a, base3 = (j0&15) + 16k
#pragma unroll
    for (int k = 0; k < 4; k++) {
        float2 w1 = g_tw[3][(j0 & 15) + 16 * k];
        float2 w2 = cmul(w1, w1);
        float2 w3 = cmul(w2, w1);
        float2 aa = Y[0][k];
        float2 bb = cmul(Y[1][k], w1);
        float2 cc = cmul(Y[2][k], w2);
        float2 dd = cmul(Y[3][k], w3);
        RAD4(aa, bb, cc, dd, Z[0][k], Z[1][k], Z[2][k], Z[3][k]);
    }

    // Exchange 2: pos = 256*(j0>>4) + (j0&15) + 16k + 64m, padded layout
    {
        const int base2 = 256 * (j0 >> 4) + (j0 & 15);
#pragma unroll
        for (int m = 0; m < 4; m++)
#pragma unroll
            for (int k = 0; k < 4; k++)
                buf[fr][ad(base2 + 16 * k + 64 * m)] = Z[m][k];
    }
    __syncthreads();

    // ---- Stage 4 in registers, windowed write to global ----
#pragma unroll
    for (int a = 0; a < 4; a++)
#pragma unroll
        for (int bb = 0; bb < 4; bb++)
            X[a][bb] = buf[fr][ad(j0 + 64 * a + 256 * bb)];

    float2* fo = (float2*)(g_frames + (size_t)frame * NFFT);
#pragma unroll
    for (int a = 0; a < 4; a++) {
        const int j = j0 + 64 * a;
        float2 w1 = g_tw[4][j];
        float2 w2 = cmul(w1, w1);
        float2 w3 = cmul(w2, w1);
        float2 aa = X[a][0];
        float2 bb = cmul(X[a][1], w1);
        float2 cc = cmul(X[a][2], w2);
        float2 dd = cmul(X[a][3], w3);
        float2 Y0, Y1, Y2, Y3;
        RAD4(aa, bb, cc, dd, Y0, Y1, Y2, Y3);

        float2 w0t = g_winp[j];
        float2 w1t = g_winp[j + 256];
        float2 w2t = g_winp[j + 512];
        float2 w3t = g_winp[j + 768];
        fo[j]       = make_float2(Y0.x * w0t.x, Y0.y * w0t.y);
        fo[j + 256] = make_float2(Y1.x * w1t.x, Y1.y * w1t.y);
        fo[j + 512] = make_float2(Y2.x * w2t.x, Y2.y * w2t.y);
        fo[j + 768] = make_float2(Y3.x * w3t.x, Y3.y * w3t.y);
    }
#undef RAD4
}

// ---------------------------------------------------------------------------
// K3: overlap-add gather, 4 samples/thread (float4), analytic env=1.5 interior
// ---------------------------------------------------------------------------
__global__ __launch_bounds__(128) void k_ola(float* __restrict__ out)
{
    const int b = blockIdx.y;
    const int s0 = (blockIdx.x * 128 + threadIdx.x) * 4;
    const int p0 = s0 + 1024;

    int thi = p0 >> 9;
    if (thi > T_ - 1) thi = T_ - 1;
    int tlo = (p0 >= NFFT) ? ((p0 - 1536) >> 9) : 0;

    float4 acc = make_float4(0.f, 0.f, 0.f, 0.f);
    if (thi - tlo == 3) {
#pragma unroll
        for (int k = 0; k < 4; k++) {
            int t = tlo + k;
            float4 v = *(const float4*)(g_frames + ((size_t)(b * T_ + t)) * NFFT + (p0 - (t << 9)));
            acc.x += v.x; acc.y += v.y; acc.z += v.z; acc.w += v.w;
        }
        const float inv = 1.0f / 1.5f;
        acc.x *= inv; acc.y *= inv; acc.z *= inv; acc.w *= inv;
    } else {
        float4 env = make_float4(0.f, 0.f, 0.f, 0.f);
        for (int t = tlo; t <= thi; t++) {
            int off = p0 - (t << 9);
            float4 v = *(const float4*)(g_frames + ((size_t)(b * T_ + t)) * NFFT + off);
            float4 w2 = *(const float4*)&g_win2[off];
            acc.x += v.x; acc.y += v.y; acc.z += v.z; acc.w += v.w;
            env.x += w2.x; env.y += w2.y; env.z += w2.z; env.w += w2.w;
        }
        acc.x /= (env.x > 1e-11f ? env.x : 1.0f);
        acc.y /= (env.y > 1e-11f ? env.y : 1.0f);
        acc.z /= (env.z > 1e-11f ? env.z : 1.0f);
        acc.w /= (env.w > 1e-11f ? env.w : 1.0f);
    }
    *(float4*)(out + (size_t)b * OUTL + s0) = acc;
}

// ---------------------------------------------------------------------------
extern "C" void kernel_launch(void* const* d_in, const int* in_sizes, int n_in,
                              void* d_out, int out_size)
{
    const float* z    = (const float*)d_in[0];
    const float* mix  = (const float*)d_in[1];
    const float* W    = (const float*)d_in[2];
    const float* bias = (const float*)d_in[3];
    float* out = (float*)d_out;

    const int smem_gemm = (128 * ZSTR * 2) * 2;   // Za + Wt (bf16)
    cudaFuncSetAttribute(k_gemm, cudaFuncAttributeMaxDynamicSharedMemorySize, smem_gemm);

    k_init<<<8, 256>>>(bias);
    k_prep<<<NB_, 256>>>(W);
    k_gemm<<<dim3(T_ / 128, NB_, B_), 256, smem_gemm>>>(z);
    k_fft<<<B_ * T_ / 2, 128>>>(mix);
    k_ola<<<dim3(OUTL / 512, B_), 128>>>(out);
}

// round 12
// speedup vs baseline: 1.0243x; 1.0243x over previous
#include <cuda_runtime.h>
#include <cuda_bf16.h>
#include <cstdint>
#include <math.h>

#define B_    8
#define T_    2048
#define NB_   22
#define D_    128
#define O_    128      // WIDTH*2
#define FREQ_ 1025
#define NFFT  2048
#define N2    1024
#define HOP_  512
#define OUTL  1048064  // HOP*(T-1)

// Scratch (static device globals; no runtime allocation)
__device__ __nv_bfloat16 g_band[(size_t)B_ * T_ * NB_ * O_];  // band residual (no bias), bf16
__device__ __nv_bfloat16 g_Wt[(size_t)NB_ * 128 * 128];       // W transposed [n][o][d], bf16
__device__ float g_frames[(size_t)B_ * T_ * NFFT];            // windowed istft frames

// Precomputed tables (filled by k_prep every launch; deterministic)
__device__ float2 g_tw[5][256];   // FFT stage twiddles w1
__device__ float2 g_pk[1024];     // hermitian pack twiddles (cos, sin) of pi*j/1024
__device__ float  g_win2[2048];   // hann^2
__device__ float2 g_winp[1024];   // (win[2m], win[2m+1]) * (1/2048)
__device__ float4 g_mb[FREQ_];    // (bias_r*invw, bias_i*invw, invw, 0) per freq

#define ZSTR 136   // padded bf16 row stride

// ---------------------------------------------------------------------------
// K0: tables + W transpose (fp32 [n][d][o] -> bf16 [n][o][d]), 22 blocks.
// ---------------------------------------------------------------------------
__global__ __launch_bounds__(256) void k_prep(const float* __restrict__ W,
                                              const float* __restrict__ bias)
{
    const int tid = threadIdx.x;
    const int gi = blockIdx.x * 256 + tid;     // 0..5631 covers all table ranges

    if (gi < 2048) {
        float w = 0.5f - 0.5f * cospif((float)gi * (1.0f / 1024.0f));
        g_win2[gi] = w * w;
    }
    if (gi < 1024) {
        float s, c;
        sincospif((float)gi * (1.0f / 1024.0f), &s, &c);
        g_pk[gi] = make_float2(c, s);
        const float invN = 1.0f / 2048.0f;
        float w0 = 0.5f - 0.5f * cospif((float)(2 * gi) * (1.0f / 1024.0f));
        float w1 = 0.5f - 0.5f * cospif((float)(2 * gi + 1) * (1.0f / 1024.0f));
        g_winp[gi] = make_float2(w0 * invN, w1 * invN);
    }
    if (gi < 256) {
#pragma unroll
        for (int st = 0; st < 5; st++) {
            int ns = 1 << (2 * st);
            int base = gi & (ns - 1);
            float s, c;
            sincospif((float)base / (float)(2 * ns), &s, &c);
            g_tw[st][gi] = make_float2(c, s);
        }
    }
    if (gi < FREQ_) {
        int f = gi;
        float br = 0.0f, bi = 0.0f;
        int cnt = 0;
        int n1 = f / 48; if (n1 > 20) n1 = 20;
        int n0 = (f >= 63) ? (f - 63 + 47) / 48 : 0;
        for (int nn = n0; nn <= n1; nn++) {
            int col = f - 48 * nn;
            br += bias[nn * 128 + 2 * col];
            bi += bias[nn * 128 + 2 * col + 1];
            cnt++;
        }
        if (f >= 961) {
            int col = f - 961;
            br += bias[21 * 128 + 2 * col];
            bi += bias[21 * 128 + 2 * col + 1];
            cnt++;
        }
        float invw = 1.0f / (float)(cnt > 0 ? cnt : 1);
        g_mb[f] = make_float4(br * invw, bi * invw, invw, 0.0f);
    }

    // W transpose for this band
    __shared__ __nv_bfloat16 tile[128 * ZSTR];
    const int n = blockIdx.x;
#pragma unroll
    for (int i = 0; i < 64; i++) {
        int idx = tid + 256 * i;          // 0..16383
        int d = idx >> 7;
        int o = idx & 127;
        tile[o * ZSTR + d] = __float2bfloat16(W[(size_t)n * 16384 + idx]);
    }
    __syncthreads();
#pragma unroll
    for (int i = 0; i < 8; i++) {
        int idx = tid + 256 * i;          // 0..2047 uint4s
        int row = idx >> 4;
        int c = idx & 15;
        *(uint4*)(g_Wt + (size_t)n * 16384 + row * 128 + c * 8) =
            *(const uint4*)&tile[row * ZSTR + c * 8];
    }
}

// ---------------------------------------------------------------------------
// K1: band GEMM via bf16 mma.sync + ldmatrix. 64-row tiles, 4x2 warp grid
// (16 rows x 64 cols per warp, acc[8][4]) for higher occupancy.
// ---------------------------------------------------------------------------
__global__ __launch_bounds__(256) void k_gemm(const float* __restrict__ z)
{
    extern __shared__ char smraw[];
    __nv_bfloat16* Za = (__nv_bfloat16*)smraw;            // [64][ZSTR]
    __nv_bfloat16* Wt = Za + 64 * ZSTR;                   // [128][ZSTR]  (o-major)

    const int n  = blockIdx.y;
    const int b  = blockIdx.z;
    const int t0 = blockIdx.x * 64;
    const int tid = threadIdx.x;

    // Load z tile 64x128 fp32 -> bf16 smem
#pragma unroll
    for (int i = 0; i < 8; i++) {
        int idx = tid + 256 * i;          // 0..2047 float4s
        int r = idx >> 5;
        int c4 = idx & 31;
        float4 v = *(const float4*)(z + (((size_t)(b * T_ + t0 + r)) * NB_ + n) * 128 + c4 * 4);
        __nv_bfloat162* dst = (__nv_bfloat162*)&Za[r * ZSTR + c4 * 4];
        dst[0] = __float22bfloat162_rn(make_float2(v.x, v.y));
        dst[1] = __float22bfloat162_rn(make_float2(v.z, v.w));
    }

    // Copy pre-transposed Wt[n] (bf16) into smem via uint4
#pragma unroll
    for (int i = 0; i < 8; i++) {
        int idx = tid + 256 * i;          // 0..2047 uint4s
        int row = idx >> 4;
        int c = idx & 15;
        *(uint4*)&Wt[row * ZSTR + c * 8] =
            *(const uint4*)(g_Wt + (size_t)n * 16384 + row * 128 + c * 8);
    }
    __syncthreads();

    const int w    = tid >> 5;
    const int lane = tid & 31;
    const int gr   = lane >> 2;
    const int qc   = (lane & 3) * 2;
    const int wr   = w & 3;
    const int wc   = w >> 2;
    const int r0   = wr * 16;
    const int c0   = wc * 64;

    const int l8 = lane & 7;
    const int g  = lane >> 3;
    uint32_t za_s = (uint32_t)__cvta_generic_to_shared(Za);
    uint32_t wt_s = (uint32_t)__cvta_generic_to_shared(Wt);
    uint32_t aaddr  = za_s + (uint32_t)(((r0 + l8 + 8 * (g & 1)) * ZSTR + 8 * (g >> 1)) * 2);
    uint32_t baddr0 = wt_s + (uint32_t)(((c0 + l8 + 8 * (g >> 1)) * ZSTR + 8 * (g & 1)) * 2);

    float acc[8][4];
#pragma unroll
    for (int nt = 0; nt < 8; nt++)
#pragma unroll
        for (int j = 0; j < 4; j++) acc[nt][j] = 0.0f;

#pragma unroll
    for (int ks = 0; ks < 8; ks++) {
        const uint32_t koff = ks * 16 * 2;
        uint32_t a0, a1, a2, a3;
        asm volatile("ldmatrix.sync.aligned.m8n8.x4.shared.b16 {%0,%1,%2,%3}, [%4];"
                     : "=r"(a0), "=r"(a1), "=r"(a2), "=r"(a3) : "r"(aaddr + koff));
#pragma unroll
        for (int ntp = 0; ntp < 4; ntp++) {
            uint32_t q0, q1, q2, q3;
            uint32_t ba = baddr0 + (uint32_t)(ntp * 16 * ZSTR * 2) + koff;
            asm volatile("ldmatrix.sync.aligned.m8n8.x4.shared.b16 {%0,%1,%2,%3}, [%4];"
                         : "=r"(q0), "=r"(q1), "=r"(q2), "=r"(q3) : "r"(ba));
            asm volatile(
                "mma.sync.aligned.m16n8k16.row.col.f32.bf16.bf16.f32 "
                "{%0,%1,%2,%3}, {%4,%5,%6,%7}, {%8,%9}, {%0,%1,%2,%3};\n"
                : "+f"(acc[2 * ntp][0]), "+f"(acc[2 * ntp][1]),
                  "+f"(acc[2 * ntp][2]), "+f"(acc[2 * ntp][3])
                : "r"(a0), "r"(a1), "r"(a2), "r"(a3), "r"(q0), "r"(q1));
            asm volatile(
                "mma.sync.aligned.m16n8k16.row.col.f32.bf16.bf16.f32 "
                "{%0,%1,%2,%3}, {%4,%5,%6,%7}, {%8,%9}, {%0,%1,%2,%3};\n"
                : "+f"(acc[2 * ntp + 1][0]), "+f"(acc[2 * ntp + 1][1]),
                  "+f"(acc[2 * ntp + 1][2]), "+f"(acc[2 * ntp + 1][3])
                : "r"(a0), "r"(a1), "r"(a2), "r"(a3), "r"(q2), "r"(q3));
        }
    }

    const int row0 = t0 + r0 + gr;
    const int row1 = row0 + 8;
#pragma unroll
    for (int nt = 0; nt < 8; nt++) {
        const int col = c0 + nt * 8 + qc;
        __nv_bfloat16* p0 = g_band + (((size_t)(b * T_ + row0)) * NB_ + n) * 128 + col;
        __nv_bfloat16* p1 = g_band + (((size_t)(b * T_ + row1)) * NB_ + n) * 128 + col;
        *(__nv_bfloat162*)p0 = __float22bfloat162_rn(make_float2(acc[nt][0], acc[nt][1]));
        *(__nv_bfloat162*)p1 = __float22bfloat162_rn(make_float2(acc[nt][2], acc[nt][3]));
    }
}

// ---------------------------------------------------------------------------
// K2: mask gather (bf16 smem) + complex mult + irfft(2048) + window.
// 256 threads/frame, radix-4 ping-pong; stage 4 exits to global from regs.
// (round-9 version: occ ~95%, the occupancy/latency sweet spot)
// ---------------------------------------------------------------------------
__device__ __forceinline__ float2 cmul(float2 a, float2 b) {
    return make_float2(a.x * b.x - a.y * b.y, a.x * b.y + a.y * b.x);
}

__global__ __launch_bounds__(256) void k_fft(const float* __restrict__ mix)
{
    __shared__ __nv_bfloat162 bandv[NB_ * 64];   // 1408 pairs (5.5 KB)
    __shared__ float2 bufA[N2];
    __shared__ float2 bufB[N2];

    const int frame = blockIdx.x;         // b*T_ + t
    const int b = frame >> 11;
    const int t = frame & 2047;
    const int tid = threadIdx.x;

    {
        const uint4* src4 = (const uint4*)(g_band + (size_t)frame * (NB_ * O_));
        uint4* dst4 = (uint4*)bandv;
        if (tid < 176) {
            dst4[tid] = src4[tid];
            dst4[tid + 176] = src4[tid + 176];
        }
    }
    __syncthreads();

    const float* mr = mix + ((size_t)(b * 2 + 0) * T_ + t) * FREQ_;
    const float* mi = mix + ((size_t)(b * 2 + 1) * T_ + t) * FREQ_;

    auto computeX = [&](int f) -> float2 {
        float sr = 0.0f, si = 0.0f;
        int n1 = f / 48; if (n1 > 20) n1 = 20;
        int n0 = (f >= 63) ? (f - 63 + 47) / 48 : 0;
        for (int nn = n0; nn <= n1; nn++) {
            int col = f - 48 * nn;
            float2 v = __bfloat1622float2(bandv[nn * 64 + col]);
            sr += v.x; si += v.y;
        }
        if (f >= 961) {
            float2 v = __bfloat1622float2(bandv[21 * 64 + (f - 961)]);
            sr += v.x; si += v.y;
        }
        float4 mb = g_mb[f];
        float maskr = fmaf(sr, mb.z, mb.x);
        float maski = fmaf(si, mb.z, mb.y);
        float xr = mr[f], xi = mi[f];
        return make_float2(maskr * xr - maski * xi, maskr * xi + maski * xr);
    };

    auto packPair = [&](int j) {
        float2 u = computeX(j);
        float2 v = computeX(1024 - j);
        float Ar = u.x + v.x, Ai = u.y - v.y;
        float Dr = u.x - v.x, Di = u.y + v.y;
        float2 cs = g_pk[j];
        float c = cs.x, s = cs.y;
        bufA[j]        = make_float2(Ar - s * Dr - c * Di,  Ai + c * Dr - s * Di);
        bufA[1024 - j] = make_float2(Ar + s * Dr + c * Di, -Ai + c * Dr - s * Di);
    };

    packPair(tid + 256);
    if (tid == 0) {
        float x0 = computeX(0).x;
        float xn = computeX(1024).x;
        bufA[0] = make_float2(x0 + xn, x0 - xn);
        float2 u = computeX(512);
        bufA[512] = make_float2(2.0f * u.x, -2.0f * u.y);
    } else {
        packPair(tid);
    }
    __syncthreads();

    float2* src = bufA;
    float2* dst = bufB;
#pragma unroll
    for (int stage = 0; stage < 4; stage++) {
        const int shift = 2 * stage;
        const int ns = 1 << shift;
        const int j = tid;
        const int base = j & (ns - 1);

        float2 a  = src[j];
        float2 bb = src[j + 256];
        float2 cc = src[j + 512];
        float2 dd = src[j + 768];

        float2 w1 = g_tw[stage][j];
        float2 w2 = cmul(w1, w1);
        float2 w3 = cmul(w2, w1);
        bb = cmul(bb, w1);
        cc = cmul(cc, w2);
        dd = cmul(dd, w3);

        float2 p = make_float2(a.x + cc.x, a.y + cc.y);
        float2 m = make_float2(a.x - cc.x, a.y - cc.y);
        float2 q = make_float2(bb.x + dd.x, bb.y + dd.y);
        float2 r = make_float2(bb.x - dd.x, bb.y - dd.y);
        float2 ir = make_float2(-r.y, r.x);

        int idx = ((j >> shift) << (shift + 2)) + base;
        dst[idx]          = make_float2(p.x + q.x, p.y + q.y);
        dst[idx + ns]     = make_float2(m.x + ir.x, m.y + ir.y);
        dst[idx + 2 * ns] = make_float2(p.x - q.x, p.y - q.y);
        dst[idx + 3 * ns] = make_float2(m.x - ir.x, m.y - ir.y);
        __syncthreads();
        float2* tmp = src; src = dst; dst = tmp;
    }

    // Stage 4 (in-place positions): results straight from registers to global.
    {
        const int j = tid;
        float2 a  = src[j];
        float2 bb = src[j + 256];
        float2 cc = src[j + 512];
        float2 dd = src[j + 768];

        float2 w1 = g_tw[4][j];
        float2 w2 = cmul(w1, w1);
        float2 w3 = cmul(w2, w1);
        bb = cmul(bb, w1);
        cc = cmul(cc, w2);
        dd = cmul(dd, w3);

        float2 p = make_float2(a.x + cc.x, a.y + cc.y);
        float2 m = make_float2(a.x - cc.x, a.y - cc.y);
        float2 q = make_float2(bb.x + dd.x, bb.y + dd.y);
        float2 r = make_float2(bb.x - dd.x, bb.y - dd.y);
        float2 ir = make_float2(-r.y, r.x);

        float2 Y0 = make_float2(p.x + q.x, p.y + q.y);
        float2 Y1 = make_float2(m.x + ir.x, m.y + ir.y);
        float2 Y2 = make_float2(p.x - q.x, p.y - q.y);
        float2 Y3 = make_float2(m.x - ir.x, m.y - ir.y);

        float2* fo = (float2*)(g_frames + (size_t)frame * NFFT);
        float2 w0t = g_winp[j];
        float2 w1t = g_winp[j + 256];
        float2 w2t = g_winp[j + 512];
        float2 w3t = g_winp[j + 768];
        fo[j]       = make_float2(Y0.x * w0t.x, Y0.y * w0t.y);
        fo[j + 256] = make_float2(Y1.x * w1t.x, Y1.y * w1t.y);
        fo[j + 512] = make_float2(Y2.x * w2t.x, Y2.y * w2t.y);
        fo[j + 768] = make_float2(Y3.x * w3t.x, Y3.y * w3t.y);
    }
}

// ---------------------------------------------------------------------------
// K3: overlap-add gather, 4 samples/thread (float4), analytic env=1.5 interior
// ---------------------------------------------------------------------------
__global__ __launch_bounds__(128) void k_ola(float* __restrict__ out)
{
    const int b = blockIdx.y;
    const int s0 = (blockIdx.x * 128 + threadIdx.x) * 4;
    const int p0 = s0 + 1024;

    int thi = p0 >> 9;
    if (thi > T_ - 1) thi = T_ - 1;
    int tlo = (p0 >= NFFT) ? ((p0 - 1536) >> 9) : 0;

    float4 acc = make_float4(0.f, 0.f, 0.f, 0.f);
    if (thi - tlo == 3) {
#pragma unroll
        for (int k = 0; k < 4; k++) {
            int t = tlo + k;
            float4 v = *(const float4*)(g_frames + ((size_t)(b * T_ + t)) * NFFT + (p0 - (t << 9)));
            acc.x += v.x; acc.y += v.y; acc.z += v.z; acc.w += v.w;
        }
        const float inv = 1.0f / 1.5f;
        acc.x *= inv; acc.y *= inv; acc.z *= inv; acc.w *= inv;
    } else {
        float4 env = make_float4(0.f, 0.f, 0.f, 0.f);
        for (int t = tlo; t <= thi; t++) {
            int off = p0 - (t << 9);
            float4 v = *(const float4*)(g_frames + ((size_t)(b * T_ + t)) * NFFT + off);
            float4 w2 = *(const float4*)&g_win2[off];
            acc.x += v.x; acc.y += v.y; acc.z += v.z; acc.w += v.w;
            env.x += w2.x; env.y += w2.y; env.z += w2.z; env.w += w2.w;
        }
        acc.x /= (env.x > 1e-11f ? env.x : 1.0f);
        acc.y /= (env.y > 1e-11f ? env.y : 1.0f);
        acc.z /= (env.z > 1e-11f ? env.z : 1.0f);
        acc.w /= (env.w > 1e-11f ? env.w : 1.0f);
    }
    *(float4*)(out + (size_t)b * OUTL + s0) = acc;
}

// ---------------------------------------------------------------------------
extern "C" void kernel_launch(void* const* d_in, const int* in_sizes, int n_in,
                              void* d_out, int out_size)
{
    const float* z    = (const float*)d_in[0];
    const float* mix  = (const float*)d_in[1];
    const float* W    = (const float*)d_in[2];
    const float* bias = (const float*)d_in[3];
    float* out = (float*)d_out;

    const int smem_gemm = (64 * ZSTR + 128 * ZSTR) * 2;   // 52224 B
    cudaFuncSetAttribute(k_gemm, cudaFuncAttributeMaxDynamicSharedMemorySize, smem_gemm);

    k_prep<<<NB_, 256>>>(W, bias);
    k_gemm<<<dim3(T_ / 64, NB_, B_), 256, smem_gemm>>>(z);
    k_fft<<<B_ * T_, 256>>>(mix);
    k_ola<<<dim3(OUTL / 512, B_), 128>>>(out);
}